// round 2
// baseline (speedup 1.0000x reference)
#include <cuda_runtime.h>
#include <cstdint>

#define NV   50000
#define ME   10000
#define NNZt 1600000
#define D    128

// Scratch (static device globals — no runtime allocation)
__device__ float g_Xe[ME * D];      // 5.12 MB
__device__ float g_cntE[ME];
__device__ float g_Xv[NV * D];      // 25.6 MB
__device__ float g_cntV[NV];

// ---------------------------------------------------------------------------
// Zero scratch each launch (deterministic)
// ---------------------------------------------------------------------------
__global__ void zero_kernel() {
    const int nXe = ME * D / 4;
    const int nXv = NV * D / 4;
    const int nCE = ME / 4;
    const int nCV = NV / 4;
    int i = blockIdx.x * blockDim.x + threadIdx.x;
    float4 z = make_float4(0.f, 0.f, 0.f, 0.f);
    if (i < nXe) {
        reinterpret_cast<float4*>(g_Xe)[i] = z;
    } else if (i < nXe + nXv) {
        reinterpret_cast<float4*>(g_Xv)[i - nXe] = z;
    } else if (i < nXe + nXv + nCE) {
        reinterpret_cast<float4*>(g_cntE)[i - nXe - nXv] = z;
    } else if (i < nXe + nXv + nCE + nCV) {
        reinterpret_cast<float4*>(g_cntV)[i - nXe - nXv - nCE] = z;
    }
}

__device__ __forceinline__ void red_add_v4(float* dst, float4 v) {
    asm volatile("red.global.add.v4.f32 [%0], {%1, %2, %3, %4};"
                 :: "l"(dst), "f"(v.x), "f"(v.y), "f"(v.z), "f"(v.w)
                 : "memory");
}

// ---------------------------------------------------------------------------
// Pass 1: Xe_sum[e] += X[v]  for each incidence (v, e); count edges.
// One warp per incidence entry; lane handles one float4 (32*4 = 128 floats).
// ---------------------------------------------------------------------------
__global__ void scatter1_kernel(const float* __restrict__ X,
                                const int* __restrict__ vertex,
                                const int* __restrict__ edges) {
    int i = blockIdx.x * (blockDim.x >> 5) + (threadIdx.x >> 5);
    if (i >= NNZt) return;
    int lane = threadIdx.x & 31;
    int v = __ldg(vertex + i);
    int e = __ldg(edges + i);
    float4 val = reinterpret_cast<const float4*>(X + (size_t)v * D)[lane];
    red_add_v4(g_Xe + (size_t)e * D + lane * 4, val);
    if (lane == 0) atomicAdd(&g_cntE[e], 1.0f);
}

// ---------------------------------------------------------------------------
// Pass 2: Xv_sum[v] += Xe_sum[e] / cnt_e[e]; count vertices.
// (folds the edge-mean division into the gather)
// ---------------------------------------------------------------------------
__global__ void scatter2_kernel(const int* __restrict__ vertex,
                                const int* __restrict__ edges) {
    int i = blockIdx.x * (blockDim.x >> 5) + (threadIdx.x >> 5);
    if (i >= NNZt) return;
    int lane = threadIdx.x & 31;
    int v = __ldg(vertex + i);
    int e = __ldg(edges + i);
    float s = 1.0f / fmaxf(g_cntE[e], 1.0f);
    float4 val = reinterpret_cast<const float4*>(g_Xe + (size_t)e * D)[lane];
    val.x *= s; val.y *= s; val.z *= s; val.w *= s;
    red_add_v4(g_Xv + (size_t)v * D + lane * 4, val);
    if (lane == 0) atomicAdd(&g_cntV[v], 1.0f);
}

// ---------------------------------------------------------------------------
// Pass 3 (fused epilogue):
//   Xi[n]  = (1-alpha) * Xv_sum[n]/max(cnt_v[n],1) + alpha * X0[n]
//   out[n] = Xi[n] @ Weff^T,   Weff = (1-beta)*I + beta*W
// Register-tiled fp32 GEMM: 64 rows x 128 cols per block, 4x8 per thread.
// Ws stored k-major with XOR-swizzle at float4 granularity (conflict-free).
// ---------------------------------------------------------------------------
#define GR 64  // rows per block

__global__ __launch_bounds__(256) void final_kernel(
    const float* __restrict__ W,
    const float* __restrict__ X0,
    const float* __restrict__ pAlpha,
    const float* __restrict__ pBeta,
    float* __restrict__ out) {
    extern __shared__ float sm[];
    float* Ws  = sm;                 // [128][128] swizzled, Weff[c][k] at [k][swz(c)]
    float* Xis = sm + D * D;         // [64][129] padded

    const float alpha = pAlpha[0];
    const float beta  = pBeta[0];
    const float oma = 1.0f - alpha;
    const float omb = 1.0f - beta;

    const int tid  = threadIdx.x;
    const int row0 = blockIdx.x * GR;

    // Build Weff into swizzled k-major smem. Coalesced global read (idx = c*128+k).
    for (int idx = tid; idx < D * D; idx += blockDim.x) {
        int c = idx >> 7;
        int k = idx & 127;
        float w = beta * __ldg(W + idx) + ((c == k) ? omb : 0.0f);
        int c4 = c >> 2, cr = c & 3;
        Ws[k * D + (((c4 ^ (k & 31)) << 2) | cr)] = w;
    }

    // Build Xi tile: 8 rows at a time (tid>>5 selects row, lanes cover 128 floats)
    {
        int lrow = tid >> 5;
        int lane = tid & 31;
        for (int rr = 0; rr < GR; rr += 8) {
            int r = rr + lrow;
            int n = row0 + r;
            float4 xi = make_float4(0.f, 0.f, 0.f, 0.f);
            if (n < NV) {
                float rc = oma / fmaxf(g_cntV[n], 1.0f);
                float4 xv = reinterpret_cast<const float4*>(g_Xv + (size_t)n * D)[lane];
                float4 x0 = reinterpret_cast<const float4*>(X0 + (size_t)n * D)[lane];
                xi.x = xv.x * rc + alpha * x0.x;
                xi.y = xv.y * rc + alpha * x0.y;
                xi.z = xv.z * rc + alpha * x0.z;
                xi.w = xv.w * rc + alpha * x0.w;
            }
            int base = r * 129 + lane * 4;
            Xis[base + 0] = xi.x;
            Xis[base + 1] = xi.y;
            Xis[base + 2] = xi.z;
            Xis[base + 3] = xi.w;
        }
    }
    __syncthreads();

    const int rowt = tid >> 4;        // 0..15 -> 4 rows each
    const int colt = tid & 15;        // 0..15 -> 8 cols each
    const int rbase = rowt * 4;
    const int g0 = colt * 2;          // float4-group indices g0, g0+1

    float acc[4][8];
#pragma unroll
    for (int i = 0; i < 4; i++)
#pragma unroll
        for (int j = 0; j < 8; j++) acc[i][j] = 0.0f;

#pragma unroll 4
    for (int k = 0; k < D; k++) {
        float a0 = Xis[(rbase + 0) * 129 + k];
        float a1 = Xis[(rbase + 1) * 129 + k];
        float a2 = Xis[(rbase + 2) * 129 + k];
        float a3 = Xis[(rbase + 3) * 129 + k];
        int s = k & 31;
        float4 b0 = *reinterpret_cast<const float4*>(&Ws[k * D + ((g0 ^ s) << 2)]);
        float4 b1 = *reinterpret_cast<const float4*>(&Ws[k * D + (((g0 + 1) ^ s) << 2)]);
        float bv[8] = {b0.x, b0.y, b0.z, b0.w, b1.x, b1.y, b1.z, b1.w};
        float av[4] = {a0, a1, a2, a3};
#pragma unroll
        for (int i = 0; i < 4; i++)
#pragma unroll
            for (int j = 0; j < 8; j++) acc[i][j] += av[i] * bv[j];
    }

    const int cbase = colt * 8;
#pragma unroll
    for (int i = 0; i < 4; i++) {
        int n = row0 + rbase + i;
        if (n < NV) {
            float4 o0 = make_float4(acc[i][0], acc[i][1], acc[i][2], acc[i][3]);
            float4 o1 = make_float4(acc[i][4], acc[i][5], acc[i][6], acc[i][7]);
            float4* op = reinterpret_cast<float4*>(out + (size_t)n * D + cbase);
            op[0] = o0;
            op[1] = o1;
        }
    }
}

// ---------------------------------------------------------------------------
extern "C" void kernel_launch(void* const* d_in, const int* in_sizes, int n_in,
                              void* d_out, int out_size) {
    const float* X      = (const float*)d_in[0];
    const float* X0     = (const float*)d_in[1];
    const float* W      = (const float*)d_in[2];
    const float* pAlpha = (const float*)d_in[3];
    const float* pBeta  = (const float*)d_in[4];
    const int*   vertex = (const int*)d_in[5];
    const int*   edges  = (const int*)d_in[6];
    float* out = (float*)d_out;

    // zero scratch
    {
        int tot4 = ME * D / 4 + NV * D / 4 + ME / 4 + NV / 4;
        zero_kernel<<<(tot4 + 255) / 256, 256>>>();
    }
    // scatter passes: one warp per incidence entry, 8 warps per block
    scatter1_kernel<<<NNZt / 8, 256>>>(X, vertex, edges);
    scatter2_kernel<<<NNZt / 8, 256>>>(vertex, edges);

    // fused residual-mix + linear-mix
    int smem_bytes = (D * D + GR * 129) * (int)sizeof(float);  // 98,560 B
    static bool attr_set = false;
    if (!attr_set) {
        cudaFuncSetAttribute(final_kernel,
                             cudaFuncAttributeMaxDynamicSharedMemorySize, smem_bytes);
        attr_set = true;
    }
    final_kernel<<<(NV + GR - 1) / GR, 256, smem_bytes>>>(W, X0, pAlpha, pBeta, out);
}

// round 3
// speedup vs baseline: 1.3015x; 1.3015x over previous
#include <cuda_runtime.h>
#include <cstdint>

#define NV   50000
#define ME   10000
#define NNZt 1600000
#define D    128

// ---------------------------------------------------------------------------
// Static device scratch (no runtime allocation)
// ---------------------------------------------------------------------------
__device__ float g_Xe[ME * D];        // 5.12 MB   edge means
__device__ float g_Xi[NV * D];        // 25.6 MB   mixed vertex features (pass2 out)
__device__ int   g_histE[ME];
__device__ int   g_histV[NV];
__device__ int   g_offE[ME];
__device__ int   g_offV[NV];
__device__ int   g_curE[ME];
__device__ int   g_curV[NV];
__device__ int   g_vlistE[NNZt];      // vertex ids grouped by edge
__device__ int   g_elistV[NNZt];      // edge ids grouped by vertex

// ---------------------------------------------------------------------------
// Zero the histograms
// ---------------------------------------------------------------------------
__global__ void zero_hist_kernel() {
    int i = blockIdx.x * blockDim.x + threadIdx.x;
    if (i < ME) g_histE[i] = 0;
    if (i < NV) g_histV[i] = 0;
}

// ---------------------------------------------------------------------------
// Histogram of edge / vertex occurrence counts
// ---------------------------------------------------------------------------
__global__ void hist_kernel(const int* __restrict__ vertex,
                            const int* __restrict__ edges) {
    int i = blockIdx.x * blockDim.x + threadIdx.x;
    if (i >= NNZt) return;
    atomicAdd(&g_histE[__ldg(edges + i)], 1);
    atomicAdd(&g_histV[__ldg(vertex + i)], 1);
}

// ---------------------------------------------------------------------------
// Exclusive scan (block 0: edges, block 1: vertices). 1024 threads/block.
// ---------------------------------------------------------------------------
__global__ __launch_bounds__(1024) void scan_kernel() {
    const int which = blockIdx.x;
    const int n = (which == 0) ? ME : NV;
    const int* hist = (which == 0) ? g_histE : g_histV;
    int* off = (which == 0) ? g_offE : g_offV;
    int* cur = (which == 0) ? g_curE : g_curV;

    __shared__ int part[1024];
    int t = threadIdx.x;
    int chunk = (n + 1023) >> 10;
    int s0 = t * chunk;
    int s1 = s0 + chunk; if (s1 > n) s1 = n;
    if (s0 > n) s0 = n;

    int s = 0;
    for (int i = s0; i < s1; i++) s += hist[i];
    part[t] = s;
    __syncthreads();
    for (int d = 1; d < 1024; d <<= 1) {
        int v = (t >= d) ? part[t - d] : 0;
        __syncthreads();
        part[t] += v;
        __syncthreads();
    }
    int run = part[t] - s;  // exclusive prefix
    for (int i = s0; i < s1; i++) {
        off[i] = run;
        cur[i] = run;
        run += hist[i];
    }
}

// ---------------------------------------------------------------------------
// Permute incidence entries into edge-grouped and vertex-grouped lists
// ---------------------------------------------------------------------------
__global__ void permute_kernel(const int* __restrict__ vertex,
                               const int* __restrict__ edges) {
    int i = blockIdx.x * blockDim.x + threadIdx.x;
    if (i >= NNZt) return;
    int v = __ldg(vertex + i);
    int e = __ldg(edges + i);
    int p = atomicAdd(&g_curE[e], 1);
    g_vlistE[p] = v;
    int q = atomicAdd(&g_curV[v], 1);
    g_elistV[q] = e;
}

// ---------------------------------------------------------------------------
// Pass 1: Xe[e] = mean over incident vertices of X[v]. Warp per edge,
// accumulate in registers, single write. Index broadcast via shfl.
// ---------------------------------------------------------------------------
__global__ __launch_bounds__(256) void pass1_kernel(const float* __restrict__ X) {
    int e = blockIdx.x * (blockDim.x >> 5) + (threadIdx.x >> 5);
    if (e >= ME) return;
    int lane = threadIdx.x & 31;
    int beg = g_offE[e];
    int cnt = g_histE[e];
    const float4* X4 = reinterpret_cast<const float4*>(X);

    float4 acc = make_float4(0.f, 0.f, 0.f, 0.f);
    for (int base = 0; base < cnt; base += 32) {
        int m = cnt - base; if (m > 32) m = 32;
        int idx = 0;
        if (base + lane < cnt) idx = __ldg(&g_vlistE[beg + base + lane]);
        if (m == 32) {
#pragma unroll 8
            for (int j = 0; j < 32; j++) {
                int v = __shfl_sync(0xffffffffu, idx, j);
                float4 a = __ldg(&X4[(size_t)v * 32 + lane]);
                acc.x += a.x; acc.y += a.y; acc.z += a.z; acc.w += a.w;
            }
        } else {
            for (int j = 0; j < m; j++) {
                int v = __shfl_sync(0xffffffffu, idx, j);
                float4 a = __ldg(&X4[(size_t)v * 32 + lane]);
                acc.x += a.x; acc.y += a.y; acc.z += a.z; acc.w += a.w;
            }
        }
    }
    float s = (cnt > 0) ? 1.0f / (float)cnt : 0.0f;
    acc.x *= s; acc.y *= s; acc.z *= s; acc.w *= s;
    reinterpret_cast<float4*>(g_Xe)[(size_t)e * 32 + lane] = acc;
}

// ---------------------------------------------------------------------------
// Pass 2 (fused mix): Xi[n] = (1-alpha) * mean_e Xe[e] + alpha * X0[n].
// Warp per vertex.
// ---------------------------------------------------------------------------
__global__ __launch_bounds__(256) void pass2_kernel(const float* __restrict__ X0,
                                                    const float* __restrict__ pAlpha) {
    int n = blockIdx.x * (blockDim.x >> 5) + (threadIdx.x >> 5);
    if (n >= NV) return;
    int lane = threadIdx.x & 31;
    int beg = g_offV[n];
    int cnt = g_histV[n];
    const float4* E4 = reinterpret_cast<const float4*>(g_Xe);

    float4 acc = make_float4(0.f, 0.f, 0.f, 0.f);
    for (int base = 0; base < cnt; base += 32) {
        int m = cnt - base; if (m > 32) m = 32;
        int idx = 0;
        if (base + lane < cnt) idx = __ldg(&g_elistV[beg + base + lane]);
        if (m == 32) {
#pragma unroll 8
            for (int j = 0; j < 32; j++) {
                int e = __shfl_sync(0xffffffffu, idx, j);
                float4 a = __ldg(&E4[(size_t)e * 32 + lane]);
                acc.x += a.x; acc.y += a.y; acc.z += a.z; acc.w += a.w;
            }
        } else {
            for (int j = 0; j < m; j++) {
                int e = __shfl_sync(0xffffffffu, idx, j);
                float4 a = __ldg(&E4[(size_t)e * 32 + lane]);
                acc.x += a.x; acc.y += a.y; acc.z += a.z; acc.w += a.w;
            }
        }
    }
    float alpha = __ldg(pAlpha);
    float s = (cnt > 0) ? (1.0f - alpha) / (float)cnt : 0.0f;
    float4 x0 = __ldg(&reinterpret_cast<const float4*>(X0)[(size_t)n * 32 + lane]);
    float4 xi;
    xi.x = acc.x * s + alpha * x0.x;
    xi.y = acc.y * s + alpha * x0.y;
    xi.z = acc.z * s + alpha * x0.z;
    xi.w = acc.w * s + alpha * x0.w;
    reinterpret_cast<float4*>(g_Xi)[(size_t)n * 32 + lane] = xi;
}

// ---------------------------------------------------------------------------
// Final: out = Xi @ Weff^T,  Weff = (1-beta)*I + beta*W.
// 64 rows x 128 cols per block, 256 threads, 4x8 per thread.
// A read directly from global (L1-hot, vectorized); Weff in swizzled smem.
// ---------------------------------------------------------------------------
#define GR 64

__global__ __launch_bounds__(256) void final_kernel(
    const float* __restrict__ W,
    const float* __restrict__ pBeta,
    float* __restrict__ out) {
    extern __shared__ float Ws[];  // [128][128] k-major, XOR-swizzled at float4 grain

    const float beta = __ldg(pBeta);
    const float omb  = 1.0f - beta;
    const int tid  = threadIdx.x;
    const int row0 = blockIdx.x * GR;

    // Build Weff into swizzled k-major smem: Weff[c][k] -> Ws[k*128 + swz(c)]
    for (int idx = tid; idx < D * D; idx += blockDim.x) {
        int c = idx >> 7;
        int k = idx & 127;
        float w = beta * __ldg(W + idx) + ((c == k) ? omb : 0.0f);
        int c4 = c >> 2, cr = c & 3;
        Ws[k * D + (((c4 ^ (k & 31)) << 2) | cr)] = w;
    }
    __syncthreads();

    const int rowt = tid >> 4;       // 0..15 -> 4 rows each
    const int colt = tid & 15;       // 0..15 -> 8 cols each
    const int g0 = colt * 2;

    // Clamped global row indices (last block overhangs NV)
    int r[4];
#pragma unroll
    for (int i = 0; i < 4; i++) {
        int n = row0 + rowt * 4 + i;
        r[i] = (n < NV) ? n : (NV - 1);
    }

    const float4* A = reinterpret_cast<const float4*>(g_Xi);

    float acc[4][8];
#pragma unroll
    for (int i = 0; i < 4; i++)
#pragma unroll
        for (int j = 0; j < 8; j++) acc[i][j] = 0.0f;

#pragma unroll 4
    for (int k4 = 0; k4 < 32; k4++) {
        float4 a[4];
#pragma unroll
        for (int i = 0; i < 4; i++)
            a[i] = __ldg(&A[(size_t)r[i] * 32 + k4]);

#pragma unroll
        for (int kk = 0; kk < 4; kk++) {
            int k = k4 * 4 + kk;
            int s = k & 31;
            float4 b0 = *reinterpret_cast<const float4*>(&Ws[k * D + ((g0 ^ s) << 2)]);
            float4 b1 = *reinterpret_cast<const float4*>(&Ws[k * D + (((g0 + 1) ^ s) << 2)]);
            float bv[8] = {b0.x, b0.y, b0.z, b0.w, b1.x, b1.y, b1.z, b1.w};
            float av[4];
            av[0] = (kk == 0) ? a[0].x : (kk == 1) ? a[0].y : (kk == 2) ? a[0].z : a[0].w;
            av[1] = (kk == 0) ? a[1].x : (kk == 1) ? a[1].y : (kk == 2) ? a[1].z : a[1].w;
            av[2] = (kk == 0) ? a[2].x : (kk == 1) ? a[2].y : (kk == 2) ? a[2].z : a[2].w;
            av[3] = (kk == 0) ? a[3].x : (kk == 1) ? a[3].y : (kk == 2) ? a[3].z : a[3].w;
#pragma unroll
            for (int i = 0; i < 4; i++)
#pragma unroll
                for (int j = 0; j < 8; j++) acc[i][j] += av[i] * bv[j];
        }
    }

    const int cbase = colt * 8;
#pragma unroll
    for (int i = 0; i < 4; i++) {
        int n = row0 + rowt * 4 + i;
        if (n < NV) {
            float4 o0 = make_float4(acc[i][0], acc[i][1], acc[i][2], acc[i][3]);
            float4 o1 = make_float4(acc[i][4], acc[i][5], acc[i][6], acc[i][7]);
            float4* op = reinterpret_cast<float4*>(out + (size_t)n * D + cbase);
            op[0] = o0;
            op[1] = o1;
        }
    }
}

// ---------------------------------------------------------------------------
extern "C" void kernel_launch(void* const* d_in, const int* in_sizes, int n_in,
                              void* d_out, int out_size) {
    const float* X      = (const float*)d_in[0];
    const float* X0     = (const float*)d_in[1];
    const float* W      = (const float*)d_in[2];
    const float* pAlpha = (const float*)d_in[3];
    const float* pBeta  = (const float*)d_in[4];
    const int*   vertex = (const int*)d_in[5];
    const int*   edges  = (const int*)d_in[6];
    float* out = (float*)d_out;

    // CSR build
    zero_hist_kernel<<<(NV + 255) / 256, 256>>>();
    hist_kernel<<<(NNZt + 255) / 256, 256>>>(vertex, edges);
    scan_kernel<<<2, 1024>>>();
    permute_kernel<<<(NNZt + 255) / 256, 256>>>(vertex, edges);

    // Two mean-aggregation passes (register-accumulated, single write)
    pass1_kernel<<<(ME * 32 + 255) / 256, 256>>>(X);
    pass2_kernel<<<(NV * 32 + 255) / 256, 256>>>(X0, pAlpha);

    // Fused identity-mix + linear
    int smem_bytes = D * D * (int)sizeof(float);  // 65536
    static bool attr_set = false;
    if (!attr_set) {
        cudaFuncSetAttribute(final_kernel,
                             cudaFuncAttributeMaxDynamicSharedMemorySize, smem_bytes);
        attr_set = true;
    }
    final_kernel<<<(NV + GR - 1) / GR, 256, smem_bytes>>>(W, pBeta, out);
}

// round 4
// speedup vs baseline: 1.3760x; 1.0572x over previous
#include <cuda_runtime.h>
#include <cuda_fp16.h>
#include <cstdint>

#define NV   50000
#define ME   10000
#define NNZt 1600000
#define D    128

// ---------------------------------------------------------------------------
// Static device scratch
// ---------------------------------------------------------------------------
__device__ __half g_Xh[NV * D];       // 12.8 MB  fp16 copy of X
__device__ __half g_Xe[ME * D];       // 2.56 MB  edge means (fp16)
__device__ float  g_Xi[NV * D];       // 25.6 MB  mixed vertex features
__device__ int    g_histE[ME];
__device__ int    g_histV[NV];
__device__ int    g_offE[ME];
__device__ int    g_offV[NV];
__device__ int    g_curE[ME];
__device__ int    g_curV[NV];
__device__ int    g_vlistE[NNZt];
__device__ int    g_elistV[NNZt];

// ---------------------------------------------------------------------------
// Convert X to fp16 (coalesced float4 -> 4 halfs)
// ---------------------------------------------------------------------------
__global__ void convert_kernel(const float* __restrict__ X) {
    int i = blockIdx.x * blockDim.x + threadIdx.x;  // one float4 each
    const int n4 = NV * D / 4;
    if (i >= n4) return;
    float4 v = __ldg(&reinterpret_cast<const float4*>(X)[i]);
    __half2 h0 = __floats2half2_rn(v.x, v.y);
    __half2 h1 = __floats2half2_rn(v.z, v.w);
    uint2 o;
    o.x = *reinterpret_cast<unsigned*>(&h0);
    o.y = *reinterpret_cast<unsigned*>(&h1);
    reinterpret_cast<uint2*>(g_Xh)[i] = o;
}

__global__ void zero_hist_kernel() {
    int i = blockIdx.x * blockDim.x + threadIdx.x;
    if (i < ME) g_histE[i] = 0;
    if (i < NV) g_histV[i] = 0;
}

// ---------------------------------------------------------------------------
// Histogram: 4 entries per thread (int4 loads, 4 independent atomics)
// ---------------------------------------------------------------------------
__global__ void hist_kernel(const int* __restrict__ vertex,
                            const int* __restrict__ edges) {
    int i0 = (blockIdx.x * blockDim.x + threadIdx.x) * 4;
    if (i0 >= NNZt) return;
    int4 v4 = __ldg(reinterpret_cast<const int4*>(vertex + i0));
    int4 e4 = __ldg(reinterpret_cast<const int4*>(edges + i0));
    atomicAdd(&g_histE[e4.x], 1); atomicAdd(&g_histE[e4.y], 1);
    atomicAdd(&g_histE[e4.z], 1); atomicAdd(&g_histE[e4.w], 1);
    atomicAdd(&g_histV[v4.x], 1); atomicAdd(&g_histV[v4.y], 1);
    atomicAdd(&g_histV[v4.z], 1); atomicAdd(&g_histV[v4.w], 1);
}

// ---------------------------------------------------------------------------
// Exclusive scan (block 0: edges, block 1: vertices)
// ---------------------------------------------------------------------------
__global__ __launch_bounds__(1024) void scan_kernel() {
    const int which = blockIdx.x;
    const int n = (which == 0) ? ME : NV;
    const int* hist = (which == 0) ? g_histE : g_histV;
    int* off = (which == 0) ? g_offE : g_offV;
    int* cur = (which == 0) ? g_curE : g_curV;

    __shared__ int part[1024];
    int t = threadIdx.x;
    int chunk = (n + 1023) >> 10;
    int s0 = t * chunk;
    int s1 = s0 + chunk; if (s1 > n) s1 = n;
    if (s0 > n) s0 = n;

    int s = 0;
    for (int i = s0; i < s1; i++) s += hist[i];
    part[t] = s;
    __syncthreads();
    for (int d = 1; d < 1024; d <<= 1) {
        int v = (t >= d) ? part[t - d] : 0;
        __syncthreads();
        part[t] += v;
        __syncthreads();
    }
    int run = part[t] - s;
    for (int i = s0; i < s1; i++) {
        off[i] = run;
        cur[i] = run;
        run += hist[i];
    }
}

// ---------------------------------------------------------------------------
// Permute: 4 entries per thread -> 4 independent atomic+store chains
// ---------------------------------------------------------------------------
__global__ void permute_kernel(const int* __restrict__ vertex,
                               const int* __restrict__ edges) {
    int i0 = (blockIdx.x * blockDim.x + threadIdx.x) * 4;
    if (i0 >= NNZt) return;
    int4 v4 = __ldg(reinterpret_cast<const int4*>(vertex + i0));
    int4 e4 = __ldg(reinterpret_cast<const int4*>(edges + i0));
    int p0 = atomicAdd(&g_curE[e4.x], 1);
    int p1 = atomicAdd(&g_curE[e4.y], 1);
    int p2 = atomicAdd(&g_curE[e4.z], 1);
    int p3 = atomicAdd(&g_curE[e4.w], 1);
    g_vlistE[p0] = v4.x; g_vlistE[p1] = v4.y;
    g_vlistE[p2] = v4.z; g_vlistE[p3] = v4.w;
    int q0 = atomicAdd(&g_curV[v4.x], 1);
    int q1 = atomicAdd(&g_curV[v4.y], 1);
    int q2 = atomicAdd(&g_curV[v4.z], 1);
    int q3 = atomicAdd(&g_curV[v4.w], 1);
    g_elistV[q0] = e4.x; g_elistV[q1] = e4.y;
    g_elistV[q2] = e4.z; g_elistV[q3] = e4.w;
}

// ---------------------------------------------------------------------------
// Pass 1: Xe[e] = mean over incident vertices of Xh[v] (fp16 rows, 256B).
// Warp per edge; lane covers 4 features via uint2 (= 4 halfs); fp32 accum.
// ---------------------------------------------------------------------------
__global__ __launch_bounds__(256) void pass1_kernel() {
    int e = blockIdx.x * (blockDim.x >> 5) + (threadIdx.x >> 5);
    if (e >= ME) return;
    int lane = threadIdx.x & 31;
    int beg = g_offE[e];
    int cnt = g_histE[e];
    const uint2* X2 = reinterpret_cast<const uint2*>(g_Xh);

    float4 acc = make_float4(0.f, 0.f, 0.f, 0.f);
    for (int base = 0; base < cnt; base += 32) {
        int m = cnt - base; if (m > 32) m = 32;
        int idx = 0;
        if (base + lane < cnt) idx = __ldg(&g_vlistE[beg + base + lane]);
        if (m == 32) {
#pragma unroll 8
            for (int j = 0; j < 32; j++) {
                int v = __shfl_sync(0xffffffffu, idx, j);
                uint2 d = __ldg(&X2[(size_t)v * 32 + lane]);
                float2 f0 = __half22float2(*reinterpret_cast<__half2*>(&d.x));
                float2 f1 = __half22float2(*reinterpret_cast<__half2*>(&d.y));
                acc.x += f0.x; acc.y += f0.y; acc.z += f1.x; acc.w += f1.y;
            }
        } else {
            for (int j = 0; j < m; j++) {
                int v = __shfl_sync(0xffffffffu, idx, j);
                uint2 d = __ldg(&X2[(size_t)v * 32 + lane]);
                float2 f0 = __half22float2(*reinterpret_cast<__half2*>(&d.x));
                float2 f1 = __half22float2(*reinterpret_cast<__half2*>(&d.y));
                acc.x += f0.x; acc.y += f0.y; acc.z += f1.x; acc.w += f1.y;
            }
        }
    }
    float s = (cnt > 0) ? 1.0f / (float)cnt : 0.0f;
    __half2 h0 = __floats2half2_rn(acc.x * s, acc.y * s);
    __half2 h1 = __floats2half2_rn(acc.z * s, acc.w * s);
    uint2 o;
    o.x = *reinterpret_cast<unsigned*>(&h0);
    o.y = *reinterpret_cast<unsigned*>(&h1);
    reinterpret_cast<uint2*>(g_Xe)[(size_t)e * 32 + lane] = o;
}

// ---------------------------------------------------------------------------
// Pass 2 (fused mix): Xi[n] = (1-alpha) * mean_e Xe[e] + alpha * X0[n].
// Warp per vertex; gathers fp16 rows; output fp32.
// ---------------------------------------------------------------------------
__global__ __launch_bounds__(256) void pass2_kernel(const float* __restrict__ X0,
                                                    const float* __restrict__ pAlpha) {
    int n = blockIdx.x * (blockDim.x >> 5) + (threadIdx.x >> 5);
    if (n >= NV) return;
    int lane = threadIdx.x & 31;
    int beg = g_offV[n];
    int cnt = g_histV[n];
    const uint2* E2 = reinterpret_cast<const uint2*>(g_Xe);

    float4 acc = make_float4(0.f, 0.f, 0.f, 0.f);
    for (int base = 0; base < cnt; base += 32) {
        int m = cnt - base; if (m > 32) m = 32;
        int idx = 0;
        if (base + lane < cnt) idx = __ldg(&g_elistV[beg + base + lane]);
        if (m == 32) {
#pragma unroll 8
            for (int j = 0; j < 32; j++) {
                int e = __shfl_sync(0xffffffffu, idx, j);
                uint2 d = __ldg(&E2[(size_t)e * 32 + lane]);
                float2 f0 = __half22float2(*reinterpret_cast<__half2*>(&d.x));
                float2 f1 = __half22float2(*reinterpret_cast<__half2*>(&d.y));
                acc.x += f0.x; acc.y += f0.y; acc.z += f1.x; acc.w += f1.y;
            }
        } else {
            for (int j = 0; j < m; j++) {
                int e = __shfl_sync(0xffffffffu, idx, j);
                uint2 d = __ldg(&E2[(size_t)e * 32 + lane]);
                float2 f0 = __half22float2(*reinterpret_cast<__half2*>(&d.x));
                float2 f1 = __half22float2(*reinterpret_cast<__half2*>(&d.y));
                acc.x += f0.x; acc.y += f0.y; acc.z += f1.x; acc.w += f1.y;
            }
        }
    }
    float alpha = __ldg(pAlpha);
    float s = (cnt > 0) ? (1.0f - alpha) / (float)cnt : 0.0f;
    float4 x0 = __ldg(&reinterpret_cast<const float4*>(X0)[(size_t)n * 32 + lane]);
    float4 xi;
    xi.x = acc.x * s + alpha * x0.x;
    xi.y = acc.y * s + alpha * x0.y;
    xi.z = acc.z * s + alpha * x0.z;
    xi.w = acc.w * s + alpha * x0.w;
    reinterpret_cast<float4*>(g_Xi)[(size_t)n * 32 + lane] = xi;
}

// ---------------------------------------------------------------------------
// Final: out = Xi @ Weff^T,  Weff = (1-beta)*I + beta*W.
// ---------------------------------------------------------------------------
#define GR 64

__global__ __launch_bounds__(256) void final_kernel(
    const float* __restrict__ W,
    const float* __restrict__ pBeta,
    float* __restrict__ out) {
    extern __shared__ float Ws[];  // [128][128] k-major, XOR-swizzled at float4 grain

    const float beta = __ldg(pBeta);
    const float omb  = 1.0f - beta;
    const int tid  = threadIdx.x;
    const int row0 = blockIdx.x * GR;

    for (int idx = tid; idx < D * D; idx += blockDim.x) {
        int c = idx >> 7;
        int k = idx & 127;
        float w = beta * __ldg(W + idx) + ((c == k) ? omb : 0.0f);
        int c4 = c >> 2, cr = c & 3;
        Ws[k * D + (((c4 ^ (k & 31)) << 2) | cr)] = w;
    }
    __syncthreads();

    const int rowt = tid >> 4;
    const int colt = tid & 15;
    const int g0 = colt * 2;

    int r[4];
#pragma unroll
    for (int i = 0; i < 4; i++) {
        int n = row0 + rowt * 4 + i;
        r[i] = (n < NV) ? n : (NV - 1);
    }

    const float4* A = reinterpret_cast<const float4*>(g_Xi);

    float acc[4][8];
#pragma unroll
    for (int i = 0; i < 4; i++)
#pragma unroll
        for (int j = 0; j < 8; j++) acc[i][j] = 0.0f;

#pragma unroll 4
    for (int k4 = 0; k4 < 32; k4++) {
        float4 a[4];
#pragma unroll
        for (int i = 0; i < 4; i++)
            a[i] = __ldg(&A[(size_t)r[i] * 32 + k4]);

#pragma unroll
        for (int kk = 0; kk < 4; kk++) {
            int k = k4 * 4 + kk;
            int s = k & 31;
            float4 b0 = *reinterpret_cast<const float4*>(&Ws[k * D + ((g0 ^ s) << 2)]);
            float4 b1 = *reinterpret_cast<const float4*>(&Ws[k * D + (((g0 + 1) ^ s) << 2)]);
            float bv[8] = {b0.x, b0.y, b0.z, b0.w, b1.x, b1.y, b1.z, b1.w};
            float av[4];
            av[0] = (kk == 0) ? a[0].x : (kk == 1) ? a[0].y : (kk == 2) ? a[0].z : a[0].w;
            av[1] = (kk == 0) ? a[1].x : (kk == 1) ? a[1].y : (kk == 2) ? a[1].z : a[1].w;
            av[2] = (kk == 0) ? a[2].x : (kk == 1) ? a[2].y : (kk == 2) ? a[2].z : a[2].w;
            av[3] = (kk == 0) ? a[3].x : (kk == 1) ? a[3].y : (kk == 2) ? a[3].z : a[3].w;
#pragma unroll
            for (int i = 0; i < 4; i++)
#pragma unroll
                for (int j = 0; j < 8; j++) acc[i][j] += av[i] * bv[j];
        }
    }

    const int cbase = colt * 8;
#pragma unroll
    for (int i = 0; i < 4; i++) {
        int n = row0 + rowt * 4 + i;
        if (n < NV) {
            float4 o0 = make_float4(acc[i][0], acc[i][1], acc[i][2], acc[i][3]);
            float4 o1 = make_float4(acc[i][4], acc[i][5], acc[i][6], acc[i][7]);
            float4* op = reinterpret_cast<float4*>(out + (size_t)n * D + cbase);
            op[0] = o0;
            op[1] = o1;
        }
    }
}

// ---------------------------------------------------------------------------
extern "C" void kernel_launch(void* const* d_in, const int* in_sizes, int n_in,
                              void* d_out, int out_size) {
    const float* X      = (const float*)d_in[0];
    const float* X0     = (const float*)d_in[1];
    const float* W      = (const float*)d_in[2];
    const float* pAlpha = (const float*)d_in[3];
    const float* pBeta  = (const float*)d_in[4];
    const int*   vertex = (const int*)d_in[5];
    const int*   edges  = (const int*)d_in[6];
    float* out = (float*)d_out;

    convert_kernel<<<(NV * D / 4 + 255) / 256, 256>>>(X);
    zero_hist_kernel<<<(NV + 255) / 256, 256>>>();
    hist_kernel<<<(NNZt / 4 + 255) / 256, 256>>>(vertex, edges);
    scan_kernel<<<2, 1024>>>();
    permute_kernel<<<(NNZt / 4 + 255) / 256, 256>>>(vertex, edges);

    pass1_kernel<<<(ME * 32 + 255) / 256, 256>>>();
    pass2_kernel<<<(NV * 32 + 255) / 256, 256>>>(X0, pAlpha);

    int smem_bytes = D * D * (int)sizeof(float);  // 65536
    static bool attr_set = false;
    if (!attr_set) {
        cudaFuncSetAttribute(final_kernel,
                             cudaFuncAttributeMaxDynamicSharedMemorySize, smem_bytes);
        attr_set = true;
    }
    final_kernel<<<(NV + GR - 1) / GR, 256, smem_bytes>>>(W, pBeta, out);
}